// round 11
// baseline (speedup 1.0000x reference)
#include <cuda_runtime.h>
#include <cstdint>

#define PP     8
#define FF     64
#define SB     200
#define TPB    128
#define VPITCH 256u            // bytes per V row (chunk-XOR swizzled)
#define VROWS  208             // padded to 13 m16 tiles
#define U_OFF  (VROWS * 256)   // 53248
#define UPITCH 272u            // 68 floats: conflict-free b-frag LDS.32
#define SMEMB  (U_OFF + (int)(PP * UPITCH))   // 55424 -> 4 CTAs/SM

typedef unsigned long long ull;

static __device__ __forceinline__ void cp16(uint32_t dst, const void* src) {
    asm volatile("cp.async.cg.shared.global [%0], [%1], 16;" :: "r"(dst), "l"(src) : "memory");
}
static __device__ __forceinline__ void mbar_wait(uint32_t addr) {
    asm volatile(
        "{\n\t.reg .pred P;\n\t"
        "LAB_%=:\n\t"
        "mbarrier.try_wait.parity.acquire.cta.shared::cta.b64 P, [%0], 0, 0x989680;\n\t"
        "@!P bra LAB_%=;\n\t}"
        :: "r"(addr) : "memory");
}
static __device__ __forceinline__ uint32_t lds_tf32(uint32_t addr) {
    float v; asm volatile("ld.shared.f32 %0, [%1];" : "=f"(v) : "r"(addr));
    uint32_t o; asm("cvt.rna.tf32.f32 %0, %1;" : "=r"(o) : "f"(v));
    return o;
}
static __device__ __forceinline__ void mma_tf32(float& d0, float& d1, float& d2, float& d3,
                                                uint32_t a0, uint32_t a1, uint32_t a2, uint32_t a3,
                                                uint32_t b0, uint32_t b1) {
    asm volatile("mma.sync.aligned.m16n8k8.row.col.f32.tf32.tf32.f32 "
                 "{%0,%1,%2,%3}, {%4,%5,%6,%7}, {%8,%9}, {%0,%1,%2,%3};"
                 : "+f"(d0), "+f"(d1), "+f"(d2), "+f"(d3)
                 : "r"(a0), "r"(a1), "r"(a2), "r"(a3), "r"(b0), "r"(b1));
}

// Per-row epilogue: lane q of each quad holds scores for cols {2q, 2q+1}.
static __device__ __forceinline__ void emit_row(long long b, int row, int q,
                                                float r0, float r1,
                                                float* __restrict__ pred,
                                                float* __restrict__ scores) {
    float m = fmaxf(r0, r1);
    m = fmaxf(m, __shfl_xor_sync(0xFFFFFFFFu, m, 1));
    m = fmaxf(m, __shfl_xor_sync(0xFFFFFFFFu, m, 2));
    const float e0 = __expf(r0 - m), e1 = __expf(r1 - m);
    float s = e0 + e1;
    s += __shfl_xor_sync(0xFFFFFFFFu, s, 1);
    s += __shfl_xor_sync(0xFFFFFFFFu, s, 2);
    const float inv = 1.f / s;
    const float a0 = e0 * inv, a1 = e1 * inv;
    float p = fmaf(a1, r1, a0 * r0);
    p += __shfl_xor_sync(0xFFFFFFFFu, p, 1);
    p += __shfl_xor_sync(0xFFFFFFFFu, p, 2);
    if (row < SB) {
        const long long g = b * SB + row;
        *(float2*)(scores + g * (long long)PP + 2 * q) = make_float2(a0, a1);
        if (q == 0) pred[g] = p;
    }
}

__global__ __launch_bounds__(TPB, 4) void cf_kernel(
    const int*   __restrict__ user,     // [B]
    const int*   __restrict__ items,    // [B,SB]
    const float* __restrict__ ufac,     // [N_USERS, PP, FF]
    const float* __restrict__ ifac,     // [N_ITEMS, FF]
    float*       __restrict__ pred,     // [B,SB]
    float*       __restrict__ scores)   // [B,SB,PP]
{
    extern __shared__ __align__(16) char smem[];
    __shared__ __align__(8) ull mbar;

    const int tid  = threadIdx.x;
    const int wid  = tid >> 5;
    const int lane = tid & 31;
    const int q    = lane & 3;      // thread-in-group
    const int gp   = lane >> 2;     // group id (row within m8)
    const long long b = blockIdx.x;

    const uint32_t sv = (uint32_t)__cvta_generic_to_shared(smem);
    const uint32_t su = sv + U_OFF;
    const uint32_t mb = (uint32_t)__cvta_generic_to_shared(&mbar);

    if (tid == 0)
        asm volatile("mbarrier.init.shared.b64 [%0], %1;" :: "r"(mb), "r"(TPB) : "memory");
    __syncthreads();

    // Zero pad rows 200..207 (8 rows x 256B = 128 float4; one per thread)
    {
        const int r = 200 + (tid >> 4);
        *(float4*)(smem + r * 256 + (tid & 15) * 16) = make_float4(0.f, 0.f, 0.f, 0.f);
    }

    // ---- Gather V: 200 rows x 16 chunks of 16B, chunk-XOR swizzle ----
    const int* itr = items + b * SB;
    #pragma unroll
    for (int k = 0; k < 25; k++) {
        const int i = tid + k * TPB;        // 25*128 = 3200 exactly
        const int r = i >> 4;
        const int c = i & 15;
        const int idx = __ldg(itr + r);
        cp16(sv + (uint32_t)(r * 256) + (uint32_t)((c ^ (r & 15)) << 4),
             ifac + (long long)idx * FF + (c << 2));
    }
    // ---- Gather U: 8 rows x 16 chunks, pitch 272 ----
    {
        const float* ubp = ufac + (long long)__ldg(user + b) * (PP * FF);
        const int p = tid >> 4, c = tid & 15;
        cp16(su + (uint32_t)p * UPITCH + (uint32_t)(c << 4), ubp + p * FF + (c << 2));
    }
    asm volatile("cp.async.mbarrier.arrive.noinc.shared::cta.b64 [%0];" :: "r"(mb) : "memory");
    __syncthreads();          // zero-STS visibility across warps
    mbar_wait(mb);

    // ---- B fragments (U), loaded once per warp: b0=U[n=gp][k=q+8j], b1=U[gp][q+4+8j] ----
    uint32_t bf0[8], bf1[8];
    #pragma unroll
    for (int j = 0; j < 8; j++) {
        bf0[j] = lds_tf32(su + (uint32_t)gp * UPITCH + (uint32_t)((q + 8 * j) << 2));
        bf1[j] = lds_tf32(su + (uint32_t)gp * UPITCH + (uint32_t)((q + 4 + 8 * j) << 2));
    }

    // ---- Tiles: warp w handles tiles w, w+4, w+8 (+12 for w==0) ----
    for (int tile = wid; tile < 13; tile += 4) {
        const int rA = tile * 16 + gp;
        const int rB = rA + 8;
        const uint32_t baseA = sv + (uint32_t)(rA * 256);
        const uint32_t baseB = sv + (uint32_t)(rB * 256);
        const int mA = rA & 15, mB = rB & 15;

        float d0 = 0.f, d1 = 0.f, d2 = 0.f, d3 = 0.f;
        #pragma unroll
        for (int j = 0; j < 8; j++) {
            // A-frag: a0=V[rA][q+8j], a1=V[rB][q+8j], a2=V[rA][q+4+8j], a3=V[rB][q+4+8j]
            const uint32_t a0 = lds_tf32(baseA + (uint32_t)(((2 * j)     ^ mA) << 4) + (q << 2));
            const uint32_t a1 = lds_tf32(baseB + (uint32_t)(((2 * j)     ^ mB) << 4) + (q << 2));
            const uint32_t a2 = lds_tf32(baseA + (uint32_t)(((2 * j + 1) ^ mA) << 4) + (q << 2));
            const uint32_t a3 = lds_tf32(baseB + (uint32_t)(((2 * j + 1) ^ mB) << 4) + (q << 2));
            mma_tf32(d0, d1, d2, d3, a0, a1, a2, a3, bf0[j], bf1[j]);
        }

        emit_row(b, rA, q, d0, d1, pred, scores);
        emit_row(b, rB, q, d2, d3, pred, scores);
    }
}

extern "C" void kernel_launch(void* const* d_in, const int* in_sizes, int n_in,
                              void* d_out, int out_size) {
    const int*   user  = (const int*)d_in[0];
    const int*   items = (const int*)d_in[1];
    const float* ufac  = (const float*)d_in[2];
    const float* ifac  = (const float*)d_in[3];

    const int B = in_sizes[0];

    float* out    = (float*)d_out;
    float* pred   = out;                        // [B,SB]
    float* scores = out + (long long)B * SB;    // [B,SB,PP]

    cudaFuncSetAttribute(cf_kernel, cudaFuncAttributeMaxDynamicSharedMemorySize, SMEMB);

    cf_kernel<<<B, TPB, SMEMB>>>(user, items, ufac, ifac, pred, scores);
}

// round 12
// speedup vs baseline: 1.3552x; 1.3552x over previous
#include <cuda_runtime.h>
#include <cstdint>

#define PP     8
#define FF     64
#define SB     200
#define TPB    256
#define VROWS  208             // padded to 13 m16 tiles
#define U_OFF  (VROWS * 256)   // 53248
#define UPITCH 272u            // 68 floats: conflict-free b-frag LDS.32
#define SMEMB  (U_OFF + (int)(PP * UPITCH))   // 55424 -> 4 CTAs/SM

typedef unsigned long long ull;

static __device__ __forceinline__ void cp16(uint32_t dst, const void* src) {
    asm volatile("cp.async.cg.shared.global [%0], [%1], 16;" :: "r"(dst), "l"(src) : "memory");
}
static __device__ __forceinline__ void mbar_wait(uint32_t addr) {
    asm volatile(
        "{\n\t.reg .pred P;\n\t"
        "LAB_%=:\n\t"
        "mbarrier.try_wait.parity.acquire.cta.shared::cta.b64 P, [%0], 0, 0x989680;\n\t"
        "@!P bra LAB_%=;\n\t}"
        :: "r"(addr) : "memory");
}
static __device__ __forceinline__ uint32_t lds_tf32(uint32_t addr) {
    float v; asm volatile("ld.shared.f32 %0, [%1];" : "=f"(v) : "r"(addr));
    uint32_t o; asm("cvt.rna.tf32.f32 %0, %1;" : "=r"(o) : "f"(v));
    return o;
}
static __device__ __forceinline__ void mma_tf32(float& d0, float& d1, float& d2, float& d3,
                                                uint32_t a0, uint32_t a1, uint32_t a2, uint32_t a3,
                                                uint32_t b0, uint32_t b1) {
    asm volatile("mma.sync.aligned.m16n8k8.row.col.f32.tf32.tf32.f32 "
                 "{%0,%1,%2,%3}, {%4,%5,%6,%7}, {%8,%9}, {%0,%1,%2,%3};"
                 : "+f"(d0), "+f"(d1), "+f"(d2), "+f"(d3)
                 : "r"(a0), "r"(a1), "r"(a2), "r"(a3), "r"(b0), "r"(b1));
}

// Per-row epilogue: lane q of each quad holds scores for cols {2q, 2q+1}.
static __device__ __forceinline__ void emit_row(long long b, int row, int q,
                                                float r0, float r1,
                                                float* __restrict__ pred,
                                                float* __restrict__ scores) {
    float m = fmaxf(r0, r1);
    m = fmaxf(m, __shfl_xor_sync(0xFFFFFFFFu, m, 1));
    m = fmaxf(m, __shfl_xor_sync(0xFFFFFFFFu, m, 2));
    const float e0 = __expf(r0 - m), e1 = __expf(r1 - m);
    float s = e0 + e1;
    s += __shfl_xor_sync(0xFFFFFFFFu, s, 1);
    s += __shfl_xor_sync(0xFFFFFFFFu, s, 2);
    const float inv = 1.f / s;
    const float a0 = e0 * inv, a1 = e1 * inv;
    float p = fmaf(a1, r1, a0 * r0);
    p += __shfl_xor_sync(0xFFFFFFFFu, p, 1);
    p += __shfl_xor_sync(0xFFFFFFFFu, p, 2);
    if (row < SB) {
        const long long g = b * SB + row;
        *(float2*)(scores + g * (long long)PP + 2 * q) = make_float2(a0, a1);
        if (q == 0) pred[g] = p;
    }
}

__global__ __launch_bounds__(TPB, 4) void cf_kernel(
    const int*   __restrict__ user,     // [B]
    const int*   __restrict__ items,    // [B,SB]
    const float* __restrict__ ufac,     // [N_USERS, PP, FF]
    const float* __restrict__ ifac,     // [N_ITEMS, FF]
    float*       __restrict__ pred,     // [B,SB]
    float*       __restrict__ scores)   // [B,SB,PP]
{
    extern __shared__ __align__(16) char smem[];
    __shared__ __align__(8) ull mbar;

    const int tid  = threadIdx.x;
    const int wid  = tid >> 5;
    const int lane = tid & 31;
    const int q    = lane & 3;      // thread-in-group
    const int gp   = lane >> 2;     // group id (row within m8)
    const long long b = blockIdx.x;

    const uint32_t sv = (uint32_t)__cvta_generic_to_shared(smem);
    const uint32_t su = sv + U_OFF;
    const uint32_t mb = (uint32_t)__cvta_generic_to_shared(&mbar);

    if (tid == 0)
        asm volatile("mbarrier.init.shared.b64 [%0], %1;" :: "r"(mb), "r"(TPB) : "memory");
    __syncthreads();

    // Zero pad rows 200..207 (8 rows x 256B = 128 float4)
    if (tid < 128) {
        const int r = 200 + (tid >> 4);
        *(float4*)(smem + r * 256 + (tid & 15) * 16) = make_float4(0.f, 0.f, 0.f, 0.f);
    }

    // ---- Gather V: 200 rows x 16 chunks of 16B, chunk-XOR swizzle ----
    const int* itr = items + b * SB;
    #pragma unroll
    for (int k = 0; k < 13; k++) {
        const int i = tid + k * TPB;        // 3200 total
        if (i < SB * 16) {
            const int r = i >> 4;
            const int c = i & 15;
            const int idx = __ldg(itr + r);
            cp16(sv + (uint32_t)(r * 256) + (uint32_t)((c ^ (r & 15)) << 4),
                 ifac + (long long)idx * FF + (c << 2));
        }
    }
    // ---- Gather U: 8 rows x 16 chunks, pitch 272 ----
    if (tid < 128) {
        const float* ubp = ufac + (long long)__ldg(user + b) * (PP * FF);
        const int p = tid >> 4, c = tid & 15;
        cp16(su + (uint32_t)p * UPITCH + (uint32_t)(c << 4), ubp + p * FF + (c << 2));
    }
    asm volatile("cp.async.mbarrier.arrive.noinc.shared::cta.b64 [%0];" :: "r"(mb) : "memory");
    __syncthreads();          // zero-STS visibility across warps
    mbar_wait(mb);

    // ---- B fragments (U), once per warp: b0=U[n=gp][k=q+8j], b1=U[gp][q+4+8j] ----
    uint32_t bf0[8], bf1[8];
    #pragma unroll
    for (int j = 0; j < 8; j++) {
        bf0[j] = lds_tf32(su + (uint32_t)gp * UPITCH + (uint32_t)((q + 8 * j) << 2));
        bf1[j] = lds_tf32(su + (uint32_t)gp * UPITCH + (uint32_t)((q + 4 + 8 * j) << 2));
    }

    // ---- Tiles: warp w handles tiles w and w+8 ----
    for (int tile = wid; tile < 13; tile += 8) {
        const int rA = tile * 16 + gp;
        const int rB = rA + 8;
        const uint32_t baseA = sv + (uint32_t)(rA * 256);
        const uint32_t baseB = sv + (uint32_t)(rB * 256);
        const int mA = rA & 15, mB = rB & 15;

        float d0 = 0.f, d1 = 0.f, d2 = 0.f, d3 = 0.f;
        #pragma unroll
        for (int j = 0; j < 8; j++) {
            const uint32_t a0 = lds_tf32(baseA + (uint32_t)(((2 * j)     ^ mA) << 4) + (q << 2));
            const uint32_t a1 = lds_tf32(baseB + (uint32_t)(((2 * j)     ^ mB) << 4) + (q << 2));
            const uint32_t a2 = lds_tf32(baseA + (uint32_t)(((2 * j + 1) ^ mA) << 4) + (q << 2));
            const uint32_t a3 = lds_tf32(baseB + (uint32_t)(((2 * j + 1) ^ mB) << 4) + (q << 2));
            mma_tf32(d0, d1, d2, d3, a0, a1, a2, a3, bf0[j], bf1[j]);
        }

        emit_row(b, rA, q, d0, d1, pred, scores);
        emit_row(b, rB, q, d2, d3, pred, scores);
    }
}

extern "C" void kernel_launch(void* const* d_in, const int* in_sizes, int n_in,
                              void* d_out, int out_size) {
    const int*   user  = (const int*)d_in[0];
    const int*   items = (const int*)d_in[1];
    const float* ufac  = (const float*)d_in[2];
    const float* ifac  = (const float*)d_in[3];

    const int B = in_sizes[0];

    float* out    = (float*)d_out;
    float* pred   = out;                        // [B,SB]
    float* scores = out + (long long)B * SB;    // [B,SB,PP]

    cudaFuncSetAttribute(cf_kernel, cudaFuncAttributeMaxDynamicSharedMemorySize, SMEMB);

    cf_kernel<<<B, TPB, SMEMB>>>(user, items, ufac, ifac, pred, scores);
}

// round 13
// speedup vs baseline: 1.4894x; 1.0990x over previous
#include <cuda_runtime.h>
#include <cstdint>

#define PP     8
#define FF     64
#define SB     200
#define TPB    256
#define VROWS  208             // padded to 13 m16 tiles
#define U_OFF  (VROWS * 256)   // 53248
#define UPITCH 272u            // 68 floats: conflict-free b-frag LDS.32
#define SMEMB  (U_OFF + (int)(PP * UPITCH))   // 55424 -> 4 CTAs/SM

typedef unsigned long long ull;

static __device__ __forceinline__ void cp16(uint32_t dst, const void* src) {
    asm volatile("cp.async.cg.shared.global [%0], [%1], 16;" :: "r"(dst), "l"(src) : "memory");
}
static __device__ __forceinline__ void mbar_wait(uint32_t addr) {
    asm volatile(
        "{\n\t.reg .pred P;\n\t"
        "LAB_%=:\n\t"
        "mbarrier.try_wait.parity.acquire.cta.shared::cta.b64 P, [%0], 0, 0x989680;\n\t"
        "@!P bra LAB_%=;\n\t}"
        :: "r"(addr) : "memory");
}
// raw f32 bits -> tf32 operand (HW truncates to top 19 bits; no CVT instruction)
static __device__ __forceinline__ uint32_t lds_raw(uint32_t addr) {
    uint32_t v; asm volatile("ld.shared.b32 %0, [%1];" : "=r"(v) : "r"(addr));
    return v;
}
static __device__ __forceinline__ void mma_tf32(float& d0, float& d1, float& d2, float& d3,
                                                uint32_t a0, uint32_t a1, uint32_t a2, uint32_t a3,
                                                uint32_t b0, uint32_t b1) {
    asm volatile("mma.sync.aligned.m16n8k8.row.col.f32.tf32.tf32.f32 "
                 "{%0,%1,%2,%3}, {%4,%5,%6,%7}, {%8,%9}, {%0,%1,%2,%3};"
                 : "+f"(d0), "+f"(d1), "+f"(d2), "+f"(d3)
                 : "r"(a0), "r"(a1), "r"(a2), "r"(a3), "r"(b0), "r"(b1));
}

// Per-row epilogue: lane q of quad holds scores for cols {2q, 2q+1}.
// Logits are tiny (|r| << 1) -> exp(r) safe without max subtraction; softmax invariant.
static __device__ __forceinline__ void emit_row(long long b, int row, int q,
                                                float r0, float r1,
                                                float* __restrict__ pred,
                                                float* __restrict__ scores) {
    const float e0 = __expf(r0), e1 = __expf(r1);
    float s = e0 + e1;
    float p = fmaf(e1, r1, e0 * r0);          // softmax numerator for pred
    // two independent 2-level butterfly reductions (dual-issue)
    s += __shfl_xor_sync(0xFFFFFFFFu, s, 1);
    p += __shfl_xor_sync(0xFFFFFFFFu, p, 1);
    s += __shfl_xor_sync(0xFFFFFFFFu, s, 2);
    p += __shfl_xor_sync(0xFFFFFFFFu, p, 2);
    const float inv = 1.f / s;
    if (row < SB) {
        const long long g = b * SB + row;
        *(float2*)(scores + g * (long long)PP + 2 * q) = make_float2(e0 * inv, e1 * inv);
        if (q == 0) pred[g] = p * inv;
    }
}

__global__ __launch_bounds__(TPB, 4) void cf_kernel(
    const int*   __restrict__ user,     // [B]
    const int*   __restrict__ items,    // [B,SB]
    const float* __restrict__ ufac,     // [N_USERS, PP, FF]
    const float* __restrict__ ifac,     // [N_ITEMS, FF]
    float*       __restrict__ pred,     // [B,SB]
    float*       __restrict__ scores)   // [B,SB,PP]
{
    extern __shared__ __align__(16) char smem[];
    __shared__ __align__(8) ull mbar;

    const int tid  = threadIdx.x;
    const int wid  = tid >> 5;
    const int lane = tid & 31;
    const int q    = lane & 3;
    const int gp   = lane >> 2;
    const long long b = blockIdx.x;

    const uint32_t sv = (uint32_t)__cvta_generic_to_shared(smem);
    const uint32_t su = sv + U_OFF;
    const uint32_t mb = (uint32_t)__cvta_generic_to_shared(&mbar);

    if (tid == 0)
        asm volatile("mbarrier.init.shared.b64 [%0], %1;" :: "r"(mb), "r"(TPB) : "memory");
    __syncthreads();

    // Zero pad rows 200..207
    if (tid < 128) {
        const int r = 200 + (tid >> 4);
        *(float4*)(smem + r * 256 + (tid & 15) * 16) = make_float4(0.f, 0.f, 0.f, 0.f);
    }

    // ---- Gather V: 200 rows x 16 chunks of 16B, chunk-XOR swizzle ----
    const int* itr = items + b * SB;
    #pragma unroll
    for (int k = 0; k < 13; k++) {
        const int i = tid + k * TPB;
        if (i < SB * 16) {
            const int r = i >> 4;
            const int c = i & 15;
            const int idx = __ldg(itr + r);
            cp16(sv + (uint32_t)(r * 256) + (uint32_t)((c ^ (r & 15)) << 4),
                 ifac + (long long)idx * FF + (c << 2));
        }
    }
    // ---- Gather U: 8 rows x 16 chunks, pitch 272 ----
    if (tid < 128) {
        const float* ubp = ufac + (long long)__ldg(user + b) * (PP * FF);
        const int p = tid >> 4, c = tid & 15;
        cp16(su + (uint32_t)p * UPITCH + (uint32_t)(c << 4), ubp + p * FF + (c << 2));
    }
    asm volatile("cp.async.mbarrier.arrive.noinc.shared::cta.b64 [%0];" :: "r"(mb) : "memory");
    __syncthreads();
    mbar_wait(mb);

    // ---- B fragments (U), once per warp: b0=U[n=gp][k=q+8j], b1=U[gp][q+4+8j] ----
    uint32_t bf0[8], bf1[8];
    #pragma unroll
    for (int j = 0; j < 8; j++) {
        bf0[j] = lds_raw(su + (uint32_t)gp * UPITCH + (uint32_t)((q + 8 * j) << 2));
        bf1[j] = lds_raw(su + (uint32_t)gp * UPITCH + (uint32_t)((q + 4 + 8 * j) << 2));
    }

    // ---- Tiles: warp w handles tiles w and w+8 ----
    for (int tile = wid; tile < 13; tile += 8) {
        const int rA = tile * 16 + gp;
        const int rB = rA + 8;
        const uint32_t baseA = sv + (uint32_t)(rA * 256) + (uint32_t)(q << 2);
        const uint32_t baseB = sv + (uint32_t)(rB * 256) + (uint32_t)(q << 2);
        const int mA = rA & 15, mB = rB & 15;

        float d0 = 0.f, d1 = 0.f, d2 = 0.f, d3 = 0.f;
        #pragma unroll
        for (int j = 0; j < 8; j++) {
            const uint32_t a0 = lds_raw(baseA + (uint32_t)(((2 * j)     ^ mA) << 4));
            const uint32_t a1 = lds_raw(baseB + (uint32_t)(((2 * j)     ^ mB) << 4));
            const uint32_t a2 = lds_raw(baseA + (uint32_t)(((2 * j + 1) ^ mA) << 4));
            const uint32_t a3 = lds_raw(baseB + (uint32_t)(((2 * j + 1) ^ mB) << 4));
            mma_tf32(d0, d1, d2, d3, a0, a1, a2, a3, bf0[j], bf1[j]);
        }

        emit_row(b, rA, q, d0, d1, pred, scores);
        emit_row(b, rB, q, d2, d3, pred, scores);
    }
}

extern "C" void kernel_launch(void* const* d_in, const int* in_sizes, int n_in,
                              void* d_out, int out_size) {
    const int*   user  = (const int*)d_in[0];
    const int*   items = (const int*)d_in[1];
    const float* ufac  = (const float*)d_in[2];
    const float* ifac  = (const float*)d_in[3];

    const int B = in_sizes[0];

    float* out    = (float*)d_out;
    float* pred   = out;                        // [B,SB]
    float* scores = out + (long long)B * SB;    // [B,SB,PP]

    cudaFuncSetAttribute(cf_kernel, cudaFuncAttributeMaxDynamicSharedMemorySize, SMEMB);

    cf_kernel<<<B, TPB, SMEMB>>>(user, items, ufac, ifac, pred, scores);
}

// round 15
// speedup vs baseline: 1.5724x; 1.0557x over previous
#include <cuda_runtime.h>
#include <cstdint>

#define PP     8
#define FF     64
#define SB     200
#define TPB    256
#define VROWS  208             // padded to 13 m16 tiles
#define U_OFF  (VROWS * 256)   // 53248
#define UPITCH 272u            // 68 floats: conflict-free b-frag LDS.32
#define SMEMB  (U_OFF + (int)(PP * UPITCH))   // 55424 -> 4 CTAs/SM

typedef unsigned long long ull;

static __device__ __forceinline__ void cp16(uint32_t dst, const void* src) {
    asm volatile("cp.async.cg.shared.global [%0], [%1], 16;" :: "r"(dst), "l"(src) : "memory");
}
static __device__ __forceinline__ void mbar_wait(uint32_t addr) {
    asm volatile(
        "{\n\t.reg .pred P;\n\t"
        "LAB_%=:\n\t"
        "mbarrier.try_wait.parity.acquire.cta.shared::cta.b64 P, [%0], 0, 0x989680;\n\t"
        "@!P bra LAB_%=;\n\t}"
        :: "r"(addr) : "memory");
}
// B operand: RNA-rounded tf32 (precision margin; once per warp)
static __device__ __forceinline__ uint32_t lds_tf32(uint32_t addr) {
    float v; asm volatile("ld.shared.f32 %0, [%1];" : "=f"(v) : "r"(addr));
    uint32_t o; asm("cvt.rna.tf32.f32 %0, %1;" : "=r"(o) : "f"(v));
    return o;
}
// A fragment via ldmatrix: 16x8 tf32 tile = four 8x8-b16 matrices
static __device__ __forceinline__ void ldsm4(uint32_t& a0, uint32_t& a1,
                                             uint32_t& a2, uint32_t& a3, uint32_t addr) {
    asm volatile("ldmatrix.sync.aligned.m8n8.x4.shared.b16 {%0,%1,%2,%3}, [%4];"
                 : "=r"(a0), "=r"(a1), "=r"(a2), "=r"(a3) : "r"(addr));
}
static __device__ __forceinline__ void mma_tf32(float& d0, float& d1, float& d2, float& d3,
                                                uint32_t a0, uint32_t a1, uint32_t a2, uint32_t a3,
                                                uint32_t b0, uint32_t b1) {
    asm volatile("mma.sync.aligned.m16n8k8.row.col.f32.tf32.tf32.f32 "
                 "{%0,%1,%2,%3}, {%4,%5,%6,%7}, {%8,%9}, {%0,%1,%2,%3};"
                 : "+f"(d0), "+f"(d1), "+f"(d2), "+f"(d3)
                 : "r"(a0), "r"(a1), "r"(a2), "r"(a3), "r"(b0), "r"(b1));
}

// Per-row epilogue: lane q of quad holds scores for cols {2q, 2q+1}.
// Logits tiny (|r| << 1): exp safe without max subtraction.
static __device__ __forceinline__ void emit_row(long long b, int row, int q,
                                                float r0, float r1,
                                                float* __restrict__ pred,
                                                float* __restrict__ scores) {
    const float e0 = __expf(r0), e1 = __expf(r1);
    float s = e0 + e1;
    float p = fmaf(e1, r1, e0 * r0);
    s += __shfl_xor_sync(0xFFFFFFFFu, s, 1);
    p += __shfl_xor_sync(0xFFFFFFFFu, p, 1);
    s += __shfl_xor_sync(0xFFFFFFFFu, s, 2);
    p += __shfl_xor_sync(0xFFFFFFFFu, p, 2);
    const float inv = 1.f / s;
    if (row < SB) {
        const long long g = b * SB + row;
        *(float2*)(scores + g * (long long)PP + 2 * q) = make_float2(e0 * inv, e1 * inv);
        if (q == 0) pred[g] = p * inv;
    }
}

__global__ __launch_bounds__(TPB, 4) void cf_kernel(
    const int*   __restrict__ user,     // [B]
    const int*   __restrict__ items,    // [B,SB]
    const float* __restrict__ ufac,     // [N_USERS, PP, FF]
    const float* __restrict__ ifac,     // [N_ITEMS, FF]
    float*       __restrict__ pred,     // [B,SB]
    float*       __restrict__ scores)   // [B,SB,PP]
{
    extern __shared__ __align__(16) char smem[];
    __shared__ __align__(8) ull mbar;

    const int tid  = threadIdx.x;
    const int wid  = tid >> 5;
    const int lane = tid & 31;
    const int q    = lane & 3;
    const int gp   = lane >> 2;
    const long long b = blockIdx.x;

    const uint32_t sv = (uint32_t)__cvta_generic_to_shared(smem);
    const uint32_t su = sv + U_OFF;
    const uint32_t mb = (uint32_t)__cvta_generic_to_shared(&mbar);

    if (tid == 0)
        asm volatile("mbarrier.init.shared.b64 [%0], %1;" :: "r"(mb), "r"(TPB) : "memory");
    __syncthreads();

    // Zero pad rows 200..207
    if (tid < 128) {
        const int r = 200 + (tid >> 4);
        *(float4*)(smem + r * 256 + (tid & 15) * 16) = make_float4(0.f, 0.f, 0.f, 0.f);
    }

    // ---- Gather V: 200 rows x 16 chunks of 16B, chunk-XOR swizzle ----
    const int* itr = items + b * SB;
    #pragma unroll
    for (int k = 0; k < 13; k++) {
        const int i = tid + k * TPB;
        if (i < SB * 16) {
            const int r = i >> 4;
            const int c = i & 15;
            const int idx = __ldg(itr + r);
            cp16(sv + (uint32_t)(r * 256) + (uint32_t)((c ^ (r & 15)) << 4),
                 ifac + (long long)idx * FF + (c << 2));
        }
    }
    // ---- Gather U: 8 rows x 16 chunks, pitch 272 ----
    if (tid < 128) {
        const float* ubp = ufac + (long long)__ldg(user + b) * (PP * FF);
        const int p = tid >> 4, c = tid & 15;
        cp16(su + (uint32_t)p * UPITCH + (uint32_t)(c << 4), ubp + p * FF + (c << 2));
    }
    asm volatile("cp.async.mbarrier.arrive.noinc.shared::cta.b64 [%0];" :: "r"(mb) : "memory");
    __syncthreads();
    mbar_wait(mb);

    // ---- B fragments (U), once per warp, RNA-rounded ----
    uint32_t bf0[8], bf1[8];
    #pragma unroll
    for (int j = 0; j < 8; j++) {
        bf0[j] = lds_tf32(su + (uint32_t)gp * UPITCH + (uint32_t)((q + 8 * j) << 2));
        bf1[j] = lds_tf32(su + (uint32_t)gp * UPITCH + (uint32_t)((q + 4 + 8 * j) << 2));
    }

    // ldmatrix lane roles: lanes 0-7 -> mat0 (rows 0-7, chunk 2j), 8-15 -> mat1 (rows 8-15),
    // 16-23 -> mat2 (rows 0-7, chunk 2j+1), 24-31 -> mat3 (rows 8-15, chunk 2j+1)
    const int lrow15 = lane & 15;
    const int lhi    = lane >> 4;

    // ---- Tiles: warp w handles tiles w and w+8 ----
    for (int tile = wid; tile < 13; tile += 8) {
        const int lrow = tile * 16 + lrow15;
        const uint32_t rbase = sv + (uint32_t)(lrow * 256);
        const int mr = lrow & 15;

        float d0a = 0.f, d1a = 0.f, d2a = 0.f, d3a = 0.f;   // even k-steps
        float d0b = 0.f, d1b = 0.f, d2b = 0.f, d3b = 0.f;   // odd k-steps
        #pragma unroll
        for (int j = 0; j < 8; j++) {
            uint32_t a0, a1, a2, a3;
            ldsm4(a0, a1, a2, a3, rbase + (uint32_t)(((2 * j + lhi) ^ mr) << 4));
            if (j & 1) mma_tf32(d0b, d1b, d2b, d3b, a0, a1, a2, a3, bf0[j], bf1[j]);
            else       mma_tf32(d0a, d1a, d2a, d3a, a0, a1, a2, a3, bf0[j], bf1[j]);
        }

        const int rA = tile * 16 + gp;
        // D frag: (d0,d1) = row gp cols {2q,2q+1}; (d2,d3) = row gp+8
        emit_row(b, rA,     q, d0a + d0b, d1a + d1b, pred, scores);
        emit_row(b, rA + 8, q, d2a + d2b, d3a + d3b, pred, scores);
    }
}

extern "C" void kernel_launch(void* const* d_in, const int* in_sizes, int n_in,
                              void* d_out, int out_size) {
    const int*   user  = (const int*)d_in[0];
    const int*   items = (const int*)d_in[1];
    const float* ufac  = (const float*)d_in[2];
    const float* ifac  = (const float*)d_in[3];

    const int B = in_sizes[0];

    float* out    = (float*)d_out;
    float* pred   = out;                        // [B,SB]
    float* scores = out + (long long)B * SB;    // [B,SB,PP]

    cudaFuncSetAttribute(cf_kernel, cudaFuncAttributeMaxDynamicSharedMemorySize, SMEMB);

    cf_kernel<<<B, TPB, SMEMB>>>(user, items, ufac, ifac, pred, scores);
}

// round 16
// speedup vs baseline: 1.7661x; 1.1232x over previous
#include <cuda_runtime.h>
#include <cstdint>

#define PP     8
#define FF     64
#define SB     200
#define TPB    256
#define VPITCH 272u                     // 17 x 16B: odd pitch -> conflict-free ldmatrix
#define U_OFF  (SB * (int)VPITCH)       // 54400
#define SMEMB  (U_OFF + PP * (int)VPITCH)   // 56576 -> 4 CTAs/SM
#define TXB    ((SB + PP) * 256)        // 53248 expected tx bytes

typedef unsigned long long ull;

static __device__ __forceinline__ void bulk_cp(uint32_t dst, const void* src,
                                               uint32_t bytes, uint32_t mbar) {
    asm volatile("cp.async.bulk.shared::cta.global.mbarrier::complete_tx::bytes [%0], [%1], %2, [%3];"
                 :: "r"(dst), "l"(src), "r"(bytes), "r"(mbar) : "memory");
}
static __device__ __forceinline__ void mbar_wait(uint32_t addr) {
    asm volatile(
        "{\n\t.reg .pred P;\n\t"
        "LAB_%=:\n\t"
        "mbarrier.try_wait.parity.acquire.cta.shared::cta.b64 P, [%0], 0, 0x989680;\n\t"
        "@!P bra LAB_%=;\n\t}"
        :: "r"(addr) : "memory");
}
// B operand: RNA-rounded tf32 (precision margin; once per warp)
static __device__ __forceinline__ uint32_t lds_tf32(uint32_t addr) {
    float v; asm volatile("ld.shared.f32 %0, [%1];" : "=f"(v) : "r"(addr));
    uint32_t o; asm("cvt.rna.tf32.f32 %0, %1;" : "=r"(o) : "f"(v));
    return o;
}
static __device__ __forceinline__ void ldsm4(uint32_t& a0, uint32_t& a1,
                                             uint32_t& a2, uint32_t& a3, uint32_t addr) {
    asm volatile("ldmatrix.sync.aligned.m8n8.x4.shared.b16 {%0,%1,%2,%3}, [%4];"
                 : "=r"(a0), "=r"(a1), "=r"(a2), "=r"(a3) : "r"(addr));
}
static __device__ __forceinline__ void mma_tf32(float& d0, float& d1, float& d2, float& d3,
                                                uint32_t a0, uint32_t a1, uint32_t a2, uint32_t a3,
                                                uint32_t b0, uint32_t b1) {
    asm volatile("mma.sync.aligned.m16n8k8.row.col.f32.tf32.tf32.f32 "
                 "{%0,%1,%2,%3}, {%4,%5,%6,%7}, {%8,%9}, {%0,%1,%2,%3};"
                 : "+f"(d0), "+f"(d1), "+f"(d2), "+f"(d3)
                 : "r"(a0), "r"(a1), "r"(a2), "r"(a3), "r"(b0), "r"(b1));
}

// Per-row epilogue; all lanes run shuffles, 'wr' guards the stores.
static __device__ __forceinline__ void emit_row(long long b, int row, int q, bool wr,
                                                float r0, float r1,
                                                float* __restrict__ pred,
                                                float* __restrict__ scores) {
    const float e0 = __expf(r0), e1 = __expf(r1);
    float s = e0 + e1;
    float p = fmaf(e1, r1, e0 * r0);
    s += __shfl_xor_sync(0xFFFFFFFFu, s, 1);
    p += __shfl_xor_sync(0xFFFFFFFFu, p, 1);
    s += __shfl_xor_sync(0xFFFFFFFFu, s, 2);
    p += __shfl_xor_sync(0xFFFFFFFFu, p, 2);
    const float inv = 1.f / s;
    if (wr) {
        const long long g = b * SB + row;
        *(float2*)(scores + g * (long long)PP + 2 * q) = make_float2(e0 * inv, e1 * inv);
        if (q == 0) pred[g] = p * inv;
    }
}

__global__ __launch_bounds__(TPB, 4) void cf_kernel(
    const int*   __restrict__ user,     // [B]
    const int*   __restrict__ items,    // [B,SB]
    const float* __restrict__ ufac,     // [N_USERS, PP, FF]
    const float* __restrict__ ifac,     // [N_ITEMS, FF]
    float*       __restrict__ pred,     // [B,SB]
    float*       __restrict__ scores)   // [B,SB,PP]
{
    extern __shared__ __align__(16) char smem[];
    __shared__ __align__(8) ull mbar;

    const int tid  = threadIdx.x;
    const int wid  = tid >> 5;
    const int lane = tid & 31;
    const int q    = lane & 3;
    const int gp   = lane >> 2;
    const long long b = blockIdx.x;

    const uint32_t sv = (uint32_t)__cvta_generic_to_shared(smem);
    const uint32_t su = sv + (uint32_t)U_OFF;
    const uint32_t mb = (uint32_t)__cvta_generic_to_shared(&mbar);

    if (tid == 0)
        asm volatile("mbarrier.init.shared.b64 [%0], 1;" :: "r"(mb) : "memory");
    __syncthreads();

    // ---- Gather via bulk DMA: one 256B copy per V row + 8 for U rows ----
    if (tid == 0)
        asm volatile("mbarrier.arrive.expect_tx.shared.b64 _, [%0], %1;"
                     :: "r"(mb), "r"(TXB) : "memory");
    if (tid < SB) {
        const int idx = __ldg(items + b * SB + tid);
        bulk_cp(sv + (uint32_t)tid * VPITCH, ifac + (long long)idx * FF, 256, mb);
    } else if (tid < SB + PP) {
        const int p = tid - SB;
        const float* ubp = ufac + (long long)__ldg(user + b) * (PP * FF) + p * FF;
        bulk_cp(su + (uint32_t)p * VPITCH, ubp, 256, mb);
    }

    mbar_wait(mb);

    // ---- B fragments (U), once per warp, RNA-rounded ----
    uint32_t bf0[8], bf1[8];
    #pragma unroll
    for (int j = 0; j < 8; j++) {
        bf0[j] = lds_tf32(su + (uint32_t)gp * VPITCH + (uint32_t)((q + 8 * j) << 2));
        bf1[j] = lds_tf32(su + (uint32_t)gp * VPITCH + (uint32_t)((q + 4 + 8 * j) << 2));
    }

    // ldmatrix lane roles
    const int lrow15 = lane & 15;
    const int lhi    = lane >> 4;

    // ---- Tiles: warp w handles tiles w and w+8; tile 12 overlaps (rows 184..199) ----
    for (int tile = wid; tile < 13; tile += 8) {
        const int rs = (tile == 12) ? 184 : tile * 16;
        const uint32_t rbase = sv + (uint32_t)((rs + lrow15) * VPITCH) + (uint32_t)(lhi << 4);

        float d0a = 0.f, d1a = 0.f, d2a = 0.f, d3a = 0.f;   // even k-steps
        float d0b = 0.f, d1b = 0.f, d2b = 0.f, d3b = 0.f;   // odd k-steps
        #pragma unroll
        for (int j = 0; j < 8; j++) {
            uint32_t a0, a1, a2, a3;
            ldsm4(a0, a1, a2, a3, rbase + (uint32_t)(j << 5));   // immediate offsets
            if (j & 1) mma_tf32(d0b, d1b, d2b, d3b, a0, a1, a2, a3, bf0[j], bf1[j]);
            else       mma_tf32(d0a, d1a, d2a, d3a, a0, a1, a2, a3, bf0[j], bf1[j]);
        }

        const int rA = rs + gp;        // D frag: (d0,d1)=row gp; (d2,d3)=row gp+8
        const int lo = tile * 16;      // overlap rows (< lo) already emitted by tile 11
        emit_row(b, rA,     q, rA     >= lo, d0a + d0b, d1a + d1b, pred, scores);
        emit_row(b, rA + 8, q, rA + 8 >= lo, d2a + d2b, d3a + d3b, pred, scores);
    }
}

extern "C" void kernel_launch(void* const* d_in, const int* in_sizes, int n_in,
                              void* d_out, int out_size) {
    const int*   user  = (const int*)d_in[0];
    const int*   items = (const int*)d_in[1];
    const float* ufac  = (const float*)d_in[2];
    const float* ifac  = (const float*)d_in[3];

    const int B = in_sizes[0];

    float* out    = (float*)d_out;
    float* pred   = out;                        // [B,SB]
    float* scores = out + (long long)B * SB;    // [B,SB,PP]

    cudaFuncSetAttribute(cf_kernel, cudaFuncAttributeMaxDynamicSharedMemorySize, SMEMB);

    cf_kernel<<<B, TPB, SMEMB>>>(user, items, ufac, ifac, pred, scores);
}